// round 3
// baseline (speedup 1.0000x reference)
#include <cuda_runtime.h>
#include <math.h>

#define IMG   512
#define NB    4
#define NP    512
#define RCAP  37
#define PLANE (IMG * IMG)   // 262144

// Partial max-of-min-d2: g_part[batch*8 + seg] = max over 64 points of min NN d^2
__device__ float g_part[NB * 8];

// ---------------------------------------------------------------------------
// Kernel 1: blocks 0..31  -> NN partials (8 blocks/batch, 8 threads/point)
//           blocks 32..   -> zero the output (float4)
// ---------------------------------------------------------------------------
__global__ void __launch_bounds__(512)
init_kernel(const float* __restrict__ cp, float4* __restrict__ out4) {
    const int blk = blockIdx.x;
    const int t   = threadIdx.x;

    if (blk >= 32) {
        out4[(blk - 32) * 512 + t] = make_float4(0.f, 0.f, 0.f, 0.f);
        return;
    }

    const int batch = blk >> 3;
    const int seg   = blk & 7;

    __shared__ float2 pts[NP];
    __shared__ float  red[64];

    pts[t] = reinterpret_cast<const float2*>(cp)[batch * NP + t];
    __syncthreads();

    const int i   = seg * 64 + (t >> 3);   // point index for this thread group
    const int sub = t & 7;                 // which 64-slice of j
    const float2 me = pts[i];

    float mind2 = 3.0e38f;
    const int j0 = sub * 64;
#pragma unroll 8
    for (int j = j0; j < j0 + 64; ++j) {
        float dx = me.x - pts[j].x;
        float dy = me.y - pts[j].y;
        float d2 = fmaf(dy, dy, dx * dx);
        if (j != i) mind2 = fminf(mind2, d2);
    }
    // reduce min across the 8 subslices (consecutive lanes)
#pragma unroll
    for (int o = 4; o > 0; o >>= 1)
        mind2 = fminf(mind2, __shfl_down_sync(0xffffffffu, mind2, o, 8));
    if (sub == 0) red[t >> 3] = mind2;
    __syncthreads();

    // max over the 64 points of this block
    if (t < 32) {
        float v = fmaxf(red[t], red[t + 32]);
#pragma unroll
        for (int o = 16; o > 0; o >>= 1)
            v = fmaxf(v, __shfl_down_sync(0xffffffffu, v, o));
        if (t == 0) g_part[blk] = v;   // still squared distance
    }
}

// ---------------------------------------------------------------------------
// Kernel 2: splat. One block per (batch, point), 256 threads.
// lane = window column, warp strides rows by 8. Coordinates pre-scaled by 1/r
// so dist = sqrt.approx(fma(sx,sx,sy2)). Last chunk peeled with hoisted mask.
// ---------------------------------------------------------------------------
__global__ void __launch_bounds__(256)
splat_kernel(const float* __restrict__ cp,
             const float* __restrict__ alpha,
             float* __restrict__ out) {
    const int pid  = blockIdx.x;
    const int b    = pid >> 9;
    const int lane = threadIdx.x & 31;
    const int wid  = threadIdx.x >> 5;

    // fold NN partials: own batch max (-> r) and global max (-> rmax)
    float own = -1.f, all = -1.f;
#pragma unroll
    for (int k = 0; k < NB * 8; ++k) {
        float v = g_part[k];
        all = fmaxf(all, v);
        if ((k >> 3) == b) own = fmaxf(own, v);
    }
    const float r    = 2.0f * sqrtf(own);
    const float rall = 2.0f * sqrtf(all);
    const int   rmax = (int)fminf(ceilf(rall), (float)RCAP);
    const int   W2   = 2 * rmax;

    const float inv_r = 1.0f / r;

    const float2 c = reinterpret_cast<const float2*>(cp)[pid];
    const float2 a = reinterpret_cast<const float2*>(alpha)[pid];

    const float lo = (float)rmax, hi = (float)(IMG - rmax);
    const int bx = (int)floorf(fminf(fmaxf(c.x, lo), hi)) - rmax;
    const int by = (int)floorf(fminf(fmaxf(c.y, lo), hi)) - rmax;

    float* __restrict__ o0 = out + (size_t)b * 2 * PLANE;

    const int  nch  = (W2 + 31) >> 5;      // chunks per row (<= 3)
    const int  ncf  = nch - 1;             // full (unmasked) chunks
    const bool plast = ((ncf << 5) + lane) < W2;   // hoisted last-chunk mask

    // scaled coords
    const float sx0  = ((float)(bx + lane) - c.x) * inv_r;
    const float dsx  = 32.0f * inv_r;
    float       sy   = ((float)(by + wid) - c.y) * inv_r;
    const float dsy8 = 8.0f * inv_r;

    int rowoff = (by + wid) * IMG + bx + lane;

    for (int iy = wid; iy < W2; iy += 8, sy += dsy8, rowoff += 8 * IMG) {
        const float sy2 = sy * sy;
        float sx = sx0;
        int   off = rowoff;

        // full chunks: no lane mask needed
        for (int cidx = 0; cidx < ncf; ++cidx, sx += dsx, off += 32) {
            const float d2 = fmaf(sx, sx, sy2);
            float dist;
            asm("sqrt.approx.f32 %0, %1;" : "=f"(dist) : "f"(d2));
            const float om  = 1.0f - dist;          // >0 whenever used
            const float om2 = om * om;
            const float p   = fmaf(4.0f, dist, 1.0f);
            const float w   = (om2 * om2) * p;
            if (dist < 1.0f) {
                atomicAdd(o0 + off,         w * a.x);
                atomicAdd(o0 + off + PLANE, w * a.y);
            }
        }

        // peeled last chunk with hoisted lane mask
        {
            const float d2 = fmaf(sx, sx, sy2);
            float dist;
            asm("sqrt.approx.f32 %0, %1;" : "=f"(dist) : "f"(d2));
            const float om  = 1.0f - dist;
            const float om2 = om * om;
            const float p   = fmaf(4.0f, dist, 1.0f);
            const float w   = (om2 * om2) * p;
            if (plast && dist < 1.0f) {
                atomicAdd(o0 + off,         w * a.x);
                atomicAdd(o0 + off + PLANE, w * a.y);
            }
        }
    }
}

// ---------------------------------------------------------------------------
extern "C" void kernel_launch(void* const* d_in, const int* in_sizes, int n_in,
                              void* d_out, int out_size) {
    const float* cpoint = (const float*)d_in[0];  // [4,512,2]
    const float* alpha  = (const float*)d_in[1];  // [4,512,2]
    float* out = (float*)d_out;                   // [4,2,512,512]
    (void)in_sizes; (void)n_in; (void)out_size;

    // 32 NN-partial blocks + 1024 zero blocks
    init_kernel<<<32 + 1024, 512>>>(cpoint, (float4*)out);

    // one block per (batch, point)
    splat_kernel<<<NB * NP, 256>>>(cpoint, alpha, out);
}